// round 8
// baseline (speedup 1.0000x reference)
#include <cuda_runtime.h>
#include <cuda_fp16.h>

#define N_NODES 50000
#define N_EDGES 800000
#define F_IN 128
#define HID 160
#define OUT_C 128
#define NGR 64
#define OUT_DIM 10
#define NB 148            // blocks == guaranteed-resident grid (<= SM count)
#define NT 512            // threads per block
#define TT (NB * NT)      // 75776 total threads
#define NCHUNK 98         // ceil(50000/512) scan chunks

// ---------------- static scratch (no allocations allowed) ----------------
__device__ int    d_indeg[N_NODES];
__device__ int    d_ptr[N_NODES + 1];
__device__ int    d_cursor[N_NODES];
__device__ float  d_dinv[N_NODES];
__device__ int2   d_edge[N_EDGES];       // {src, norm as float bits}
__device__ uint4  d_Hh0[N_NODES * 2];    // 16 halves per node = 32B row
__device__ uint4  d_Hh1[N_NODES * 2];
__device__ float  d_c5[N_NODES];
__device__ float  d_c10[N_NODES];
__device__ float  d_P3[HID * OUT_DIM];
__device__ float  d_P2[HID * OUT_DIM];
__device__ float  d_R [F_IN * OUT_DIM];
__device__ float  d_g1[OUT_DIM];
__device__ float  d_g2[OUT_DIM];
__device__ float  d_g3[OUT_DIM];
__device__ float  d_pooled[NGR * OUT_DIM];
__device__ int    d_counts[NGR];
__device__ int    d_bsum[NCHUNK];

// ---------------- software grid barrier (self-restoring across replays) ----------------
__device__ unsigned g_count = 0;
__device__ unsigned g_phase = 0;

__device__ __forceinline__ void gsync() {
    __threadfence();                 // release: publish this thread's writes to L2
    __syncthreads();
    if (threadIdx.x == 0) {
        unsigned gen = *(volatile unsigned*)&g_phase;
        if (atomicAdd(&g_count, 1u) == NB - 1) {
            *(volatile unsigned*)&g_count = 0;
            __threadfence();
            atomicAdd(&g_phase, 1u);
        } else {
            while (*(volatile unsigned*)&g_phase == gen) __nanosleep(64);
        }
    }
    __syncthreads();
    __threadfence();                 // acquire: gpu-scope fence flushes stale L1 lines
}

// ---------------- fp16 row helpers ----------------
__device__ __forceinline__ void acc8(float* a, uint4 r, float w) {
    const half2* hp = (const half2*)&r;
    #pragma unroll
    for (int i = 0; i < 4; i++) {
        float2 f = __half22float2(hp[i]);
        a[2 * i]     += w * f.x;
        a[2 * i + 1] += w * f.y;
    }
}

__global__ __launch_bounds__(NT, 2)
void k_mega(const float* __restrict__ x, const int* __restrict__ ei,
            const int* __restrict__ batch,
            const float* __restrict__ W1, const float* __restrict__ b1,
            const float* __restrict__ W2, const float* __restrict__ b2,
            const float* __restrict__ W3, const float* __restrict__ b3,
            const float* __restrict__ fc_w, const float* __restrict__ fc_b,
            float* __restrict__ out) {
    const int tid  = threadIdx.x;
    const int gt   = blockIdx.x * NT + tid;
    const int lane = tid & 31, wid = tid >> 5;

    __shared__ int   sW[16];
    __shared__ int   sOff[NCHUNK];
    __shared__ float sR[F_IN * OUT_DIM];     // 5 KB
    __shared__ float sp[NGR * OUT_DIM];      // 2.5 KB
    __shared__ int   sc[NGR];
    __shared__ float sg1[OUT_DIM], sg2[OUT_DIM], sg3[OUT_DIM];

    // ---- P0: zero deg/pool; params1: P3 = W3 @ fc_w, g3 = b3 @ fc_w ----
    for (int i = gt; i < N_NODES; i += TT) d_indeg[i] = 0;
    for (int i = gt; i < NGR * OUT_DIM; i += TT) d_pooled[i] = 0.f;
    for (int i = gt; i < NGR; i += TT) d_counts[i] = 0;
    for (int t = gt; t < HID * OUT_DIM + OUT_DIM; t += TT) {
        if (t < HID * OUT_DIM) {
            int i = t / OUT_DIM, c = t % OUT_DIM;
            float a = 0.f;
            for (int k = 0; k < OUT_C; k++) a += W3[i * OUT_C + k] * fc_w[k * OUT_DIM + c];
            d_P3[t] = a;
        } else {
            int c = t - HID * OUT_DIM;
            float a = 0.f;
            for (int k = 0; k < OUT_C; k++) a += b3[k] * fc_w[k * OUT_DIM + c];
            d_g3[c] = a;
        }
    }
    gsync();

    // ---- P1: degree histogram (int4); params2: P2 = W2 @ P3, g2 = b2 @ P3 ----
    for (int e4 = gt; e4 < N_EDGES / 4; e4 += TT) {
        int4 d = *(const int4*)&ei[N_EDGES + e4 * 4];
        atomicAdd(&d_indeg[d.x], 1);
        atomicAdd(&d_indeg[d.y], 1);
        atomicAdd(&d_indeg[d.z], 1);
        atomicAdd(&d_indeg[d.w], 1);
    }
    for (int t = gt; t < HID * OUT_DIM + OUT_DIM; t += TT) {
        if (t < HID * OUT_DIM) {
            int i = t / OUT_DIM, c = t % OUT_DIM;
            float a = 0.f;
            for (int k = 0; k < HID; k++) a += W2[i * HID + k] * d_P3[k * OUT_DIM + c];
            d_P2[t] = a;
        } else {
            int c = t - HID * OUT_DIM;
            float a = 0.f;
            for (int k = 0; k < HID; k++) a += b2[k] * d_P3[k * OUT_DIM + c];
            d_g2[c] = a;
        }
    }
    gsync();

    // ---- P2: per-chunk exclusive scan (blocks 0..97); params3: R = W1 @ P2, g1 ----
    if (blockIdx.x < NCHUNK) {
        int i = blockIdx.x * NT + tid;
        int v = (i < N_NODES) ? d_indeg[i] : 0;
        int incl = v;
        #pragma unroll
        for (int off = 1; off < 32; off <<= 1) {
            int n = __shfl_up_sync(0xffffffffu, incl, off);
            if (lane >= off) incl += n;
        }
        if (lane == 31) sW[wid] = incl;
        __syncthreads();
        if (wid == 0) {
            int s = (lane < 16) ? sW[lane] : 0;
            #pragma unroll
            for (int off = 1; off < 16; off <<= 1) {
                int n = __shfl_up_sync(0xffffffffu, s, off);
                if (lane >= off) s += n;
            }
            if (lane < 16) sW[lane] = s;
        }
        __syncthreads();
        int wexcl = wid ? sW[wid - 1] : 0;
        if (i < N_NODES) d_ptr[i] = wexcl + incl - v;  // exclusive within chunk
        if (tid == 0) d_bsum[blockIdx.x] = sW[15];
    }
    for (int t = gt; t < F_IN * OUT_DIM + OUT_DIM; t += TT) {
        if (t < F_IN * OUT_DIM) {
            int i = t / OUT_DIM, c = t % OUT_DIM;
            float a = 0.f;
            for (int k = 0; k < HID; k++) a += W1[i * HID + k] * d_P2[k * OUT_DIM + c];
            d_R[t] = a;
        } else {
            int c = t - F_IN * OUT_DIM;
            float a = 0.f;
            for (int k = 0; k < HID; k++) a += b1[k] * d_P2[k * OUT_DIM + c];
            d_g1[c] = a;
        }
    }
    gsync();

    // ---- P3: scan fixup + cursor + dinv; init H0 = [X@R, ones, 0...] fp16 ----
    if (tid == 0) {
        int run = 0;
        for (int b = 0; b < NCHUNK; b++) { sOff[b] = run; run += d_bsum[b]; }
    }
    __syncthreads();
    for (int i = gt; i < N_NODES; i += TT) {
        int p = d_ptr[i] + sOff[i >> 9];
        d_ptr[i] = p;
        d_cursor[i] = p;
        d_dinv[i] = rsqrtf((float)(d_indeg[i] + 1));
    }
    if (gt == 0) d_ptr[N_NODES] = N_EDGES;
    for (int i = tid; i < F_IN * OUT_DIM; i += NT) sR[i] = d_R[i];
    __syncthreads();
    for (int t = gt; t < N_NODES * 2; t += TT) {
        int node = t >> 1, q = t & 1;
        const float4* xr = (const float4*)(x + node * F_IN);
        float a[8] = {0, 0, 0, 0, 0, 0, 0, 0};
        if (q == 0) {
            #pragma unroll 4
            for (int k = 0; k < F_IN / 4; k++) {
                float4 xv = xr[k];
                const float* r0 = &sR[(4 * k) * OUT_DIM];
                #pragma unroll
                for (int j = 0; j < 8; j++)
                    a[j] += xv.x * r0[j] + xv.y * r0[OUT_DIM + j]
                          + xv.z * r0[2 * OUT_DIM + j] + xv.w * r0[3 * OUT_DIM + j];
            }
        } else {
            #pragma unroll 4
            for (int k = 0; k < F_IN / 4; k++) {
                float4 xv = xr[k];
                const float* r0 = &sR[(4 * k) * OUT_DIM + 8];
                #pragma unroll
                for (int j = 0; j < 2; j++)
                    a[j] += xv.x * r0[j] + xv.y * r0[OUT_DIM + j]
                          + xv.z * r0[2 * OUT_DIM + j] + xv.w * r0[3 * OUT_DIM + j];
            }
            a[2] = 1.0f;     // ones channel (global channel 10)
        }
        uint4 o;
        half2* op = (half2*)&o;
        #pragma unroll
        for (int i = 0; i < 4; i++) op[i] = __floats2half2_rn(a[2 * i], a[2 * i + 1]);
        d_Hh0[node * 2 + q] = o;
    }
    gsync();

    // ---- P4: scatter edges into dst-CSR ----
    for (int e = gt; e < N_EDGES; e += TT) {
        int s = ei[e];
        int d = ei[N_EDGES + e];
        int p = atomicAdd(&d_cursor[d], 1);
        d_edge[p] = make_int2(s, __float_as_int(d_dinv[s] * d_dinv[d]));
    }
    gsync();

    // ---- P5..P19: 15 propagation hops, ping-pong, snapshots at hop 5/10 ----
    for (int hop = 1; hop <= 15; hop++) {
        const uint4* __restrict__ h = (hop & 1) ? d_Hh0 : d_Hh1;
        uint4* __restrict__ o       = (hop & 1) ? d_Hh1 : d_Hh0;
        int snap = (hop == 5) ? 1 : (hop == 10) ? 2 : 0;
        for (int t = gt; t < N_NODES * 2; t += TT) {
            int node = t >> 1, q = t & 1;
            int e = d_ptr[node], end = d_ptr[node + 1];
            float a[8] = {0, 0, 0, 0, 0, 0, 0, 0};
            float b[8] = {0, 0, 0, 0, 0, 0, 0, 0};
            for (; e + 1 < end; e += 2) {
                int2 m0 = d_edge[e];
                int2 m1 = d_edge[e + 1];
                uint4 r0 = h[(m0.x << 1) | q];
                uint4 r1 = h[(m1.x << 1) | q];
                acc8(a, r0, __int_as_float(m0.y));
                acc8(b, r1, __int_as_float(m1.y));
            }
            if (e < end) {
                int2 m0 = d_edge[e];
                uint4 r0 = h[(m0.x << 1) | q];
                acc8(a, r0, __int_as_float(m0.y));
            }
            float dn = d_dinv[node];
            uint4 rs = h[(node << 1) | q];
            acc8(a, rs, dn * dn);
            #pragma unroll
            for (int i = 0; i < 8; i++) a[i] += b[i];
            if (snap && q) {            // q==1 holds ch 8..15; a[2] == channel 10
                if (snap == 1) d_c5[node] = a[2];
                else           d_c10[node] = a[2];
            }
            uint4 ov;
            half2* op = (half2*)&ov;
            #pragma unroll
            for (int i = 0; i < 4; i++) op[i] = __floats2half2_rn(a[2 * i], a[2 * i + 1]);
            o[(node << 1) | q] = ov;
        }
        gsync();
    }

    // ---- P20: pooling (block-shared accumulate, then global atomics) ----
    for (int i = tid; i < NGR * OUT_DIM; i += NT) sp[i] = 0.f;
    if (tid < NGR) sc[tid] = 0;
    if (tid < OUT_DIM) { sg1[tid] = d_g1[tid]; sg2[tid] = d_g2[tid]; sg3[tid] = d_g3[tid]; }
    __syncthreads();
    for (int n = gt; n < N_NODES; n += TT) {
        int bg = batch[n];
        atomicAdd(&sc[bg], 1);
        float a10 = d_c10[n], a5 = d_c5[n];
        uint4 r0 = d_Hh1[n * 2], r1 = d_Hh1[n * 2 + 1];   // final state after hop 15
        const half2* hp0 = (const half2*)&r0;
        const half2* hp1 = (const half2*)&r1;
        float hv[10];
        float2 f;
        f = __half22float2(hp0[0]); hv[0] = f.x; hv[1] = f.y;
        f = __half22float2(hp0[1]); hv[2] = f.x; hv[3] = f.y;
        f = __half22float2(hp0[2]); hv[4] = f.x; hv[5] = f.y;
        f = __half22float2(hp0[3]); hv[6] = f.x; hv[7] = f.y;
        f = __half22float2(hp1[0]); hv[8] = f.x; hv[9] = f.y;
        #pragma unroll
        for (int c = 0; c < OUT_DIM; c++) {
            float z = hv[c] + a10 * sg1[c] + a5 * sg2[c] + sg3[c];
            atomicAdd(&sp[bg * OUT_DIM + c], z);
        }
    }
    __syncthreads();
    for (int i = tid; i < NGR * OUT_DIM; i += NT)
        if (sp[i] != 0.f) atomicAdd(&d_pooled[i], sp[i]);
    if (tid < NGR && sc[tid]) atomicAdd(&d_counts[tid], sc[tid]);
    gsync();

    // ---- P21: mean, +fc_b, log_softmax (block 0) ----
    if (blockIdx.x == 0 && tid < NGR) {
        float cnt = (float)d_counts[tid];
        if (cnt < 1.f) cnt = 1.f;
        float l[OUT_DIM];
        float m = -1e30f;
        #pragma unroll
        for (int c = 0; c < OUT_DIM; c++) {
            l[c] = d_pooled[tid * OUT_DIM + c] / cnt + fc_b[c];
            m = fmaxf(m, l[c]);
        }
        float s = 0.f;
        #pragma unroll
        for (int c = 0; c < OUT_DIM; c++) s += expf(l[c] - m);
        float lse = m + logf(s);
        #pragma unroll
        for (int c = 0; c < OUT_DIM; c++) out[tid * OUT_DIM + c] = l[c] - lse;
    }
}

// ---------------- launch ----------------
extern "C" void kernel_launch(void* const* d_in, const int* in_sizes, int n_in,
                              void* d_out, int out_size) {
    (void)in_sizes; (void)n_in; (void)out_size;
    const float* x     = (const float*)d_in[0];
    const int*   ei    = (const int*)d_in[1];     // int32 (JAX x64 disabled)
    const int*   batch = (const int*)d_in[2];     // int32
    const float* W1    = (const float*)d_in[3];
    const float* b1    = (const float*)d_in[4];
    const float* W2    = (const float*)d_in[5];
    const float* b2    = (const float*)d_in[6];
    const float* W3    = (const float*)d_in[7];
    const float* b3    = (const float*)d_in[8];
    const float* fc_w  = (const float*)d_in[9];
    const float* fc_b  = (const float*)d_in[10];
    float* out = (float*)d_out;

    k_mega<<<NB, NT>>>(x, ei, batch, W1, b1, W2, b2, W3, b3, fc_w, fc_b, out);
}

// round 9
// speedup vs baseline: 1.1773x; 1.1773x over previous
#include <cuda_runtime.h>
#include <cuda_fp16.h>

#define N_NODES 50000
#define N_EDGES 800000
#define F_IN 128
#define HID 160
#define OUT_C 128
#define NGR 64
#define OUT_DIM 10
#define NB 296            // 2 resident CTAs per SM (148 SMs)
#define NT 512            // threads per block
#define TT (NB * NT)      // 151552 total threads
#define NCHUNK 98         // ceil(50000/512) scan chunks

// ---------------- static scratch (no allocations allowed) ----------------
__device__ int    d_indeg[N_NODES];
__device__ int    d_ptr[N_NODES + 1];
__device__ int    d_cursor[N_NODES];
__device__ float  d_dinv[N_NODES];
__device__ int2   d_edge[N_EDGES];       // {src, norm as float bits}
__device__ uint4  d_Hh0[N_NODES * 2];    // 16 halves per node = 32B row
__device__ uint4  d_Hh1[N_NODES * 2];
__device__ float  d_c5[N_NODES];
__device__ float  d_c10[N_NODES];
__device__ float  d_P3[HID * OUT_DIM];
__device__ float  d_P2[HID * OUT_DIM];
__device__ float  d_R [F_IN * OUT_DIM];
__device__ float  d_g1[OUT_DIM];
__device__ float  d_g2[OUT_DIM];
__device__ float  d_g3[OUT_DIM];
__device__ float  d_pooled[NGR * OUT_DIM];
__device__ int    d_counts[NGR];
__device__ int    d_bsum[NCHUNK];

// ---------------- software grid barrier (self-restoring across replays) ----------------
__device__ unsigned g_count = 0;
__device__ unsigned g_phase = 0;

__device__ __forceinline__ void gsync() {
    __threadfence();                 // release: publish this thread's writes to L2
    __syncthreads();
    if (threadIdx.x == 0) {
        unsigned gen = *(volatile unsigned*)&g_phase;
        if (atomicAdd(&g_count, 1u) == NB - 1) {
            *(volatile unsigned*)&g_count = 0;
            __threadfence();
            atomicAdd(&g_phase, 1u);
        } else {
            while (*(volatile unsigned*)&g_phase == gen) __nanosleep(64);
        }
    }
    __syncthreads();
    __threadfence();                 // acquire: gpu-scope fence invalidates stale L1
}

// ---------------- fp16 row helpers ----------------
__device__ __forceinline__ void acc8(float* a, uint4 r, float w) {
    const half2* hp = (const half2*)&r;
    #pragma unroll
    for (int i = 0; i < 4; i++) {
        float2 f = __half22float2(hp[i]);
        a[2 * i]     += w * f.x;
        a[2 * i + 1] += w * f.y;
    }
}

__global__ __launch_bounds__(NT, 2)
void k_mega(const float* __restrict__ x, const int* __restrict__ ei,
            const int* __restrict__ batch,
            const float* __restrict__ W1, const float* __restrict__ b1,
            const float* __restrict__ W2, const float* __restrict__ b2,
            const float* __restrict__ W3, const float* __restrict__ b3,
            const float* __restrict__ fc_w, const float* __restrict__ fc_b,
            float* __restrict__ out) {
    const int tid  = threadIdx.x;
    const int gt   = blockIdx.x * NT + tid;
    const int lane = tid & 31, wid = tid >> 5;

    __shared__ int   sW[16];
    __shared__ int   sOff[NCHUNK];
    __shared__ float sR[F_IN * OUT_DIM];     // 5 KB
    __shared__ float sp[NGR * OUT_DIM];      // 2.5 KB
    __shared__ int   sc[NGR];
    __shared__ float sg1[OUT_DIM], sg2[OUT_DIM], sg3[OUT_DIM];

    // ---- P0: zero deg/pool; params1: P3 = W3 @ fc_w, g3 = b3 @ fc_w ----
    for (int i = gt; i < N_NODES; i += TT) d_indeg[i] = 0;
    for (int i = gt; i < NGR * OUT_DIM; i += TT) d_pooled[i] = 0.f;
    for (int i = gt; i < NGR; i += TT) d_counts[i] = 0;
    for (int t = gt; t < HID * OUT_DIM + OUT_DIM; t += TT) {
        if (t < HID * OUT_DIM) {
            int i = t / OUT_DIM, c = t % OUT_DIM;
            float a = 0.f;
            for (int k = 0; k < OUT_C; k++) a += W3[i * OUT_C + k] * fc_w[k * OUT_DIM + c];
            d_P3[t] = a;
        } else {
            int c = t - HID * OUT_DIM;
            float a = 0.f;
            for (int k = 0; k < OUT_C; k++) a += b3[k] * fc_w[k * OUT_DIM + c];
            d_g3[c] = a;
        }
    }
    gsync();

    // ---- P1: degree histogram (int4); params2: P2 = W2 @ P3, g2 = b2 @ P3 ----
    for (int e4 = gt; e4 < N_EDGES / 4; e4 += TT) {
        int4 d = *(const int4*)&ei[N_EDGES + e4 * 4];
        atomicAdd(&d_indeg[d.x], 1);
        atomicAdd(&d_indeg[d.y], 1);
        atomicAdd(&d_indeg[d.z], 1);
        atomicAdd(&d_indeg[d.w], 1);
    }
    for (int t = gt; t < HID * OUT_DIM + OUT_DIM; t += TT) {
        if (t < HID * OUT_DIM) {
            int i = t / OUT_DIM, c = t % OUT_DIM;
            float a = 0.f;
            for (int k = 0; k < HID; k++) a += W2[i * HID + k] * d_P3[k * OUT_DIM + c];
            d_P2[t] = a;
        } else {
            int c = t - HID * OUT_DIM;
            float a = 0.f;
            for (int k = 0; k < HID; k++) a += b2[k] * d_P3[k * OUT_DIM + c];
            d_g2[c] = a;
        }
    }
    gsync();

    // ---- P2: per-chunk exclusive scan (blocks 0..97); params3: R = W1 @ P2, g1 ----
    if (blockIdx.x < NCHUNK) {
        int i = blockIdx.x * NT + tid;
        int v = (i < N_NODES) ? d_indeg[i] : 0;
        int incl = v;
        #pragma unroll
        for (int off = 1; off < 32; off <<= 1) {
            int n = __shfl_up_sync(0xffffffffu, incl, off);
            if (lane >= off) incl += n;
        }
        if (lane == 31) sW[wid] = incl;
        __syncthreads();
        if (wid == 0) {
            int s = (lane < 16) ? sW[lane] : 0;
            #pragma unroll
            for (int off = 1; off < 16; off <<= 1) {
                int n = __shfl_up_sync(0xffffffffu, s, off);
                if (lane >= off) s += n;
            }
            if (lane < 16) sW[lane] = s;
        }
        __syncthreads();
        int wexcl = wid ? sW[wid - 1] : 0;
        if (i < N_NODES) d_ptr[i] = wexcl + incl - v;  // exclusive within chunk
        if (tid == 0) d_bsum[blockIdx.x] = sW[15];
    }
    for (int t = gt; t < F_IN * OUT_DIM + OUT_DIM; t += TT) {
        if (t < F_IN * OUT_DIM) {
            int i = t / OUT_DIM, c = t % OUT_DIM;
            float a = 0.f;
            for (int k = 0; k < HID; k++) a += W1[i * HID + k] * d_P2[k * OUT_DIM + c];
            d_R[t] = a;
        } else {
            int c = t - F_IN * OUT_DIM;
            float a = 0.f;
            for (int k = 0; k < HID; k++) a += b1[k] * d_P2[k * OUT_DIM + c];
            d_g1[c] = a;
        }
    }
    gsync();

    // ---- P3: scan fixup + cursor + dinv; init H0 = [X@R, ones, 0...] fp16 ----
    if (tid == 0) {
        int run = 0;
        for (int b = 0; b < NCHUNK; b++) { sOff[b] = run; run += d_bsum[b]; }
    }
    __syncthreads();
    for (int i = gt; i < N_NODES; i += TT) {
        int p = d_ptr[i] + sOff[i >> 9];
        d_ptr[i] = p;
        d_cursor[i] = p;
        d_dinv[i] = rsqrtf((float)(d_indeg[i] + 1));
    }
    if (gt == 0) d_ptr[N_NODES] = N_EDGES;
    for (int i = tid; i < F_IN * OUT_DIM; i += NT) sR[i] = d_R[i];
    __syncthreads();
    for (int t = gt; t < N_NODES * 2; t += TT) {
        int node = t >> 1, q = t & 1;
        const float4* xr = (const float4*)(x + node * F_IN);
        float a[8] = {0, 0, 0, 0, 0, 0, 0, 0};
        if (q == 0) {
            #pragma unroll 4
            for (int k = 0; k < F_IN / 4; k++) {
                float4 xv = xr[k];
                const float* r0 = &sR[(4 * k) * OUT_DIM];
                #pragma unroll
                for (int j = 0; j < 8; j++)
                    a[j] += xv.x * r0[j] + xv.y * r0[OUT_DIM + j]
                          + xv.z * r0[2 * OUT_DIM + j] + xv.w * r0[3 * OUT_DIM + j];
            }
        } else {
            #pragma unroll 4
            for (int k = 0; k < F_IN / 4; k++) {
                float4 xv = xr[k];
                const float* r0 = &sR[(4 * k) * OUT_DIM + 8];
                #pragma unroll
                for (int j = 0; j < 2; j++)
                    a[j] += xv.x * r0[j] + xv.y * r0[OUT_DIM + j]
                          + xv.z * r0[2 * OUT_DIM + j] + xv.w * r0[3 * OUT_DIM + j];
            }
            a[2] = 1.0f;     // ones channel (global channel 10)
        }
        uint4 o;
        half2* op = (half2*)&o;
        #pragma unroll
        for (int i = 0; i < 4; i++) op[i] = __floats2half2_rn(a[2 * i], a[2 * i + 1]);
        d_Hh0[node * 2 + q] = o;
    }
    gsync();

    // ---- P4: scatter edges into dst-CSR ----
    for (int e = gt; e < N_EDGES; e += TT) {
        int s = ei[e];
        int d = ei[N_EDGES + e];
        int p = atomicAdd(&d_cursor[d], 1);
        d_edge[p] = make_int2(s, __float_as_int(d_dinv[s] * d_dinv[d]));
    }
    gsync();

    // ---- P5..P19: 15 propagation hops, ping-pong, snapshots at hop 5/10 ----
    for (int hop = 1; hop <= 15; hop++) {
        const uint4* __restrict__ h = (hop & 1) ? d_Hh0 : d_Hh1;
        uint4* __restrict__ o       = (hop & 1) ? d_Hh1 : d_Hh0;
        int snap = (hop == 5) ? 1 : (hop == 10) ? 2 : 0;
        for (int t = gt; t < N_NODES * 2; t += TT) {
            int node = t >> 1, q = t & 1;
            int e = d_ptr[node], end = d_ptr[node + 1];
            float a[8] = {0, 0, 0, 0, 0, 0, 0, 0};
            float b[8] = {0, 0, 0, 0, 0, 0, 0, 0};
            // 4 independent gathers in flight per iteration
            for (; e + 3 < end; e += 4) {
                int2 m0 = d_edge[e];
                int2 m1 = d_edge[e + 1];
                int2 m2 = d_edge[e + 2];
                int2 m3 = d_edge[e + 3];
                uint4 r0 = h[(m0.x << 1) | q];
                uint4 r1 = h[(m1.x << 1) | q];
                uint4 r2 = h[(m2.x << 1) | q];
                uint4 r3 = h[(m3.x << 1) | q];
                acc8(a, r0, __int_as_float(m0.y));
                acc8(b, r1, __int_as_float(m1.y));
                acc8(a, r2, __int_as_float(m2.y));
                acc8(b, r3, __int_as_float(m3.y));
            }
            for (; e < end; e++) {
                int2 m0 = d_edge[e];
                uint4 r0 = h[(m0.x << 1) | q];
                acc8(a, r0, __int_as_float(m0.y));
            }
            float dn = d_dinv[node];
            uint4 rs = h[(node << 1) | q];
            acc8(a, rs, dn * dn);
            #pragma unroll
            for (int i = 0; i < 8; i++) a[i] += b[i];
            if (snap && q) {            // q==1 holds ch 8..15; a[2] == channel 10
                if (snap == 1) d_c5[node] = a[2];
                else           d_c10[node] = a[2];
            }
            uint4 ov;
            half2* op = (half2*)&ov;
            #pragma unroll
            for (int i = 0; i < 4; i++) op[i] = __floats2half2_rn(a[2 * i], a[2 * i + 1]);
            o[(node << 1) | q] = ov;
        }
        gsync();
    }

    // ---- P20: pooling (block-shared accumulate, then global atomics) ----
    for (int i = tid; i < NGR * OUT_DIM; i += NT) sp[i] = 0.f;
    if (tid < NGR) sc[tid] = 0;
    if (tid < OUT_DIM) { sg1[tid] = d_g1[tid]; sg2[tid] = d_g2[tid]; sg3[tid] = d_g3[tid]; }
    __syncthreads();
    for (int n = gt; n < N_NODES; n += TT) {
        int bg = batch[n];
        atomicAdd(&sc[bg], 1);
        float a10 = d_c10[n], a5 = d_c5[n];
        uint4 r0 = d_Hh1[n * 2], r1 = d_Hh1[n * 2 + 1];   // final state after hop 15
        const half2* hp0 = (const half2*)&r0;
        const half2* hp1 = (const half2*)&r1;
        float hv[10];
        float2 f;
        f = __half22float2(hp0[0]); hv[0] = f.x; hv[1] = f.y;
        f = __half22float2(hp0[1]); hv[2] = f.x; hv[3] = f.y;
        f = __half22float2(hp0[2]); hv[4] = f.x; hv[5] = f.y;
        f = __half22float2(hp0[3]); hv[6] = f.x; hv[7] = f.y;
        f = __half22float2(hp1[0]); hv[8] = f.x; hv[9] = f.y;
        #pragma unroll
        for (int c = 0; c < OUT_DIM; c++) {
            float z = hv[c] + a10 * sg1[c] + a5 * sg2[c] + sg3[c];
            atomicAdd(&sp[bg * OUT_DIM + c], z);
        }
    }
    __syncthreads();
    for (int i = tid; i < NGR * OUT_DIM; i += NT)
        if (sp[i] != 0.f) atomicAdd(&d_pooled[i], sp[i]);
    if (tid < NGR && sc[tid]) atomicAdd(&d_counts[tid], sc[tid]);
    gsync();

    // ---- P21: mean, +fc_b, log_softmax (block 0) ----
    if (blockIdx.x == 0 && tid < NGR) {
        float cnt = (float)d_counts[tid];
        if (cnt < 1.f) cnt = 1.f;
        float l[OUT_DIM];
        float m = -1e30f;
        #pragma unroll
        for (int c = 0; c < OUT_DIM; c++) {
            l[c] = d_pooled[tid * OUT_DIM + c] / cnt + fc_b[c];
            m = fmaxf(m, l[c]);
        }
        float s = 0.f;
        #pragma unroll
        for (int c = 0; c < OUT_DIM; c++) s += expf(l[c] - m);
        float lse = m + logf(s);
        #pragma unroll
        for (int c = 0; c < OUT_DIM; c++) out[tid * OUT_DIM + c] = l[c] - lse;
    }
}

// ---------------- launch ----------------
extern "C" void kernel_launch(void* const* d_in, const int* in_sizes, int n_in,
                              void* d_out, int out_size) {
    (void)in_sizes; (void)n_in; (void)out_size;
    const float* x     = (const float*)d_in[0];
    const int*   ei    = (const int*)d_in[1];     // int32 (JAX x64 disabled)
    const int*   batch = (const int*)d_in[2];     // int32
    const float* W1    = (const float*)d_in[3];
    const float* b1    = (const float*)d_in[4];
    const float* W2    = (const float*)d_in[5];
    const float* b2    = (const float*)d_in[6];
    const float* W3    = (const float*)d_in[7];
    const float* b3    = (const float*)d_in[8];
    const float* fc_w  = (const float*)d_in[9];
    const float* fc_b  = (const float*)d_in[10];
    float* out = (float*)d_out;

    k_mega<<<NB, NT>>>(x, ei, batch, W1, b1, W2, b2, W3, b3, fc_w, fc_b, out);
}